// round 13
// baseline (speedup 1.0000x reference)
#include <cuda_runtime.h>
#include <cuda_bf16.h>
#include <cstdint>

#define DIM     128
#define NCLS    50
#define PAIRS   25
#define WPITCH  384
#define PPITCH  64
#define NMAX    50000

typedef unsigned long long ull;
typedef unsigned int uint;

__device__ float g_P[NMAX * PPITCH];
__device__ float g_Q[NMAX * PPITCH];
__device__ int   g_idx64;

// B-operand images (bf16 hi/lo, pitch 272B = 136 bf16)
__device__ __align__(16) unsigned short g_Be_hi[56 * 136];   // W3, 56 rows
__device__ __align__(16) unsigned short g_Be_lo[56 * 136];
__device__ __align__(16) unsigned short g_Bn_hi[104 * 136];  // [W1;W2]
__device__ __align__(16) unsigned short g_Bn_lo[104 * 136];

// ---------------- helpers -------------------------------------------------
__device__ __forceinline__ uint smem_u32(const void* p) {
    uint a;
    asm("{ .reg .u64 t; cvta.to.shared.u64 t, %1; cvt.u32.u64 %0, t; }"
        : "=r"(a) : "l"(p));
    return a;
}
__device__ __forceinline__ void ldsm_x4(uint r[4], uint addr) {
    asm volatile("ldmatrix.sync.aligned.m8n8.x4.shared.b16 {%0,%1,%2,%3}, [%4];"
        : "=r"(r[0]), "=r"(r[1]), "=r"(r[2]), "=r"(r[3]) : "r"(addr));
}
__device__ __forceinline__ void ldsm_x2(uint r[2], uint addr) {
    asm volatile("ldmatrix.sync.aligned.m8n8.x2.shared.b16 {%0,%1}, [%2];"
        : "=r"(r[0]), "=r"(r[1]) : "r"(addr));
}
__device__ __forceinline__ void mma16816(float* d, const uint* a, const uint* b) {
    asm volatile("mma.sync.aligned.m16n8k16.row.col.f32.bf16.bf16.f32 "
        "{%0,%1,%2,%3}, {%4,%5,%6,%7}, {%8,%9}, {%0,%1,%2,%3};"
        : "+f"(d[0]), "+f"(d[1]), "+f"(d[2]), "+f"(d[3])
        : "r"(a[0]), "r"(a[1]), "r"(a[2]), "r"(a[3]), "r"(b[0]), "r"(b[1]));
}
__device__ __forceinline__ ull add2(ull a, ull b) {
    ull d;
    asm("add.rn.f32x2 %0, %1, %2;" : "=l"(d) : "l"(a), "l"(b));
    return d;
}
__device__ __forceinline__ void split_bf16(float a, unsigned short& hi, unsigned short& lo) {
    __nv_bfloat16 bh = __float2bfloat16(a);
    float r = a - __bfloat162float(bh);
    __nv_bfloat16 bl = __float2bfloat16(r);
    hi = reinterpret_cast<unsigned short&>(bh);
    lo = reinterpret_cast<unsigned short&>(bl);
}
__device__ __forceinline__ void split4(float4 v, uint2& hi, uint2& lo) {
    uint pk0, pk1, l0, l1;
    asm("cvt.rn.bf16x2.f32 %0, %1, %2;" : "=r"(pk0) : "f"(v.y), "f"(v.x));
    asm("cvt.rn.bf16x2.f32 %0, %1, %2;" : "=r"(pk1) : "f"(v.w), "f"(v.z));
    float rx = v.x - __uint_as_float(pk0 << 16);
    float ry = v.y - __uint_as_float(pk0 & 0xffff0000u);
    float rz = v.z - __uint_as_float(pk1 << 16);
    float rw = v.w - __uint_as_float(pk1 & 0xffff0000u);
    asm("cvt.rn.bf16x2.f32 %0, %1, %2;" : "=r"(l0) : "f"(ry), "f"(rx));
    asm("cvt.rn.bf16x2.f32 %0, %1, %2;" : "=r"(l1) : "f"(rw), "f"(rz));
    hi = make_uint2(pk0, pk1);
    lo = make_uint2(l0, l1);
}

// ==========================================================================
// Setup: idx-width detect + both B images.
// ==========================================================================
__global__ void setup_kernel(const float* __restrict__ W,
                             const void* __restrict__ src, int E)
{
    int tid = threadIdx.x + blockIdx.x * blockDim.x;
    if (tid == 0) {
        const uint* a = (const uint*)src;
        int n = E < 256 ? E : 256;
        int ok = 1;
        for (int i = 0; i < n; i++)
            if (a[2 * i + 1] != 0u) { ok = 0; break; }
        g_idx64 = ok;
    }
    for (int i = tid; i < 56 * 136; i += blockDim.x * gridDim.x) {
        int n = i / 136, k = i - n * 136;
        float v = (n < NCLS && k < DIM) ? W[n * WPITCH + 2 * DIM + k] : 0.0f;
        unsigned short h, l; split_bf16(v, h, l);
        g_Be_hi[i] = h; g_Be_lo[i] = l;
    }
    for (int i = tid; i < 104 * 136; i += blockDim.x * gridDim.x) {
        int n = i / 136, k = i - n * 136;
        float v = 0.0f;
        if (k < DIM) {
            if (n < NCLS)            v = W[n * WPITCH + k];
            else if (n < 2 * NCLS)   v = W[(n - NCLS) * WPITCH + DIM + k];
        }
        unsigned short h, l; split_bf16(v, h, l);
        g_Bn_hi[i] = h; g_Bn_lo[i] = l;
    }
}

// ==========================================================================
// Node kernel: 128 nodes/block, 256 threads (8 warps x 1 m-tile of 16),
// pipelined A staging, B copied from global image, x4-paired B ldsm.
// ==========================================================================
#define NODE_SMEM 97536
#define NT_N 13

__global__ __launch_bounds__(256, 2)
void node_kernel(const float* __restrict__ h, const float* __restrict__ b, int N)
{
    extern __shared__ __align__(16) char sb[];
    const uint ub = smem_u32(sb);
    const int tid = threadIdx.x;
    const int wid = tid >> 5;
    const int lane = tid & 31;
    const int base = blockIdx.x * 128;

    const uint A_HI0 = 0, A_LO0 = 10240, A_HI1 = 20480, A_LO1 = 30720;
    const uint B_HI = 40960, B_LO = 69248;

    for (int i = tid; i < 1768; i += 256) {
        ((float4*)(sb + B_HI))[i] = ((const float4*)g_Bn_hi)[i];
        ((float4*)(sb + B_LO))[i] = ((const float4*)g_Bn_lo)[i];
    }

    float acc[NT_N][4];
#pragma unroll
    for (int nt = 0; nt < NT_N; nt++)
#pragma unroll
        for (int r = 0; r < 4; r++) acc[nt][r] = 0.0f;

    int pm[4], pk[4], gn[4];
#pragma unroll
    for (int it = 0; it < 4; it++) {
        int i = it * 256 + tid;
        pm[it] = i >> 3; pk[it] = (i & 7) * 4;
        int g = base + pm[it]; if (g >= N) g = N - 1;
        gn[it] = g;
    }

    float4 pf[4];
#pragma unroll
    for (int it = 0; it < 4; it++)
        pf[it] = *(const float4*)(h + (size_t)gn[it] * DIM + pk[it]);
#pragma unroll
    for (int it = 0; it < 4; it++) {
        uint2 hi, lo; split4(pf[it], hi, lo);
        *(uint2*)(sb + A_HI0 + pm[it] * 80 + pk[it] * 2) = hi;
        *(uint2*)(sb + A_LO0 + pm[it] * 80 + pk[it] * 2) = lo;
    }
#pragma unroll
    for (int it = 0; it < 4; it++)
        pf[it] = *(const float4*)(h + (size_t)gn[it] * DIM + 32 + pk[it]);
    __syncthreads();

#pragma unroll
    for (int ch = 0; ch < 4; ch++) {
        if (ch < 3) {
            const uint nh = (ch & 1) ? A_HI0 : A_HI1;
            const uint nl = (ch & 1) ? A_LO0 : A_LO1;
#pragma unroll
            for (int it = 0; it < 4; it++) {
                uint2 hi, lo; split4(pf[it], hi, lo);
                *(uint2*)(sb + nh + pm[it] * 80 + pk[it] * 2) = hi;
                *(uint2*)(sb + nl + pm[it] * 80 + pk[it] * 2) = lo;
            }
            if (ch < 2) {
#pragma unroll
                for (int it = 0; it < 4; it++)
                    pf[it] = *(const float4*)(h + (size_t)gn[it] * DIM
                                              + (ch + 2) * 32 + pk[it]);
            }
        }
        const uint AH = (ch & 1) ? A_HI1 : A_HI0;
        const uint AL = (ch & 1) ? A_LO1 : A_LO0;
#pragma unroll
        for (int kt = 0; kt < 2; kt++) {
            int ktg = ch * 2 + kt;
            uint ahi[4], alo[4];
            uint row = wid * 16 + (lane & 15);
            uint off = row * 80 + (lane >> 4) * 16 + kt * 32;
            ldsm_x4(ahi, ub + AH + off);
            ldsm_x4(alo, ub + AL + off);
            uint brow = ((lane >> 4) << 3) + (lane & 7);
            uint bk   = ((lane >> 3) & 1) * 16 + ktg * 32;
#pragma unroll
            for (int ntp = 0; ntp < 6; ntp++) {
                uint boff = (ntp * 16 + brow) * 272 + bk;
                uint bh4[4], bl4[4];
                ldsm_x4(bh4, ub + B_HI + boff);
                ldsm_x4(bl4, ub + B_LO + boff);
                mma16816(acc[2 * ntp],     ahi, bh4);
                mma16816(acc[2 * ntp],     alo, bh4);
                mma16816(acc[2 * ntp],     ahi, bl4);
                mma16816(acc[2 * ntp + 1], ahi, bh4 + 2);
                mma16816(acc[2 * ntp + 1], alo, bh4 + 2);
                mma16816(acc[2 * ntp + 1], ahi, bl4 + 2);
            }
            {
                uint l = lane & 15;
                uint boff = (96 + (l & 7)) * 272 + ((l >> 3) & 1) * 16 + ktg * 32;
                uint bhi[2], blo[2];
                ldsm_x2(bhi, ub + B_HI + boff);
                ldsm_x2(blo, ub + B_LO + boff);
                mma16816(acc[12], ahi, bhi);
                mma16816(acc[12], alo, bhi);
                mma16816(acc[12], ahi, blo);
            }
        }
        __syncthreads();
    }

    float* sOutF = (float*)sb;
    {
        int r0 = wid * 16 + (lane >> 2);
        int c0 = 2 * (lane & 3);
#pragma unroll
        for (int nt = 0; nt < NT_N; nt++) {
            *(float2*)(sOutF + r0 * 104 + nt * 8 + c0) =
                make_float2(acc[nt][0], acc[nt][1]);
            *(float2*)(sOutF + (r0 + 8) * 104 + nt * 8 + c0) =
                make_float2(acc[nt][2], acc[nt][3]);
        }
    }
    __syncthreads();

    const ull* sOutU = (const ull*)sb;   // pitch 52 ull
    const ull* b2 = (const ull*)b;
    int rv = N - base; if (rv > 128) rv = 128;
    if (rv > 0) {
        for (int i = tid; i < rv * PAIRS; i += 256) {
            int m = i / PAIRS, c = i - m * PAIRS;
            *(ull*)(g_P + (size_t)(base + m) * PPITCH + 2 * c) =
                add2(sOutU[m * 52 + c], b2[c]);
            *(ull*)(g_Q + (size_t)(base + m) * PPITCH + 2 * c) =
                sOutU[m * 52 + 25 + c];
        }
    }
}

// ==========================================================================
// Edge kernel: 384 edges/block, 256 threads (8 warps x 3 m-tiles of 16),
// x4-paired B ldsm, WIDENED 16B epilogue gather.
// smem: A_HI @0 (30720), A_LO @30720 (30720),
//       B_HI @61440 (15232), B_LO @76672 (15232),
//       sS @91904 (1536), sD @93440 (1536) -> 94976.
// sOut overlays @0: 384x56 f32 = 86016.
// ==========================================================================
#define EDGE_SMEM 94976
#define NT_E 7
#define EBLK 384

__global__ __launch_bounds__(256, 2)
void edge_kernel(const float* __restrict__ efeat,
                 const void* __restrict__ src,
                 const void* __restrict__ dst,
                 float* __restrict__ out, int E)
{
    extern __shared__ __align__(16) char sb[];
    const uint ub = smem_u32(sb);
    const int tid = threadIdx.x;
    const int wid = tid >> 5;
    const int lane = tid & 31;
    const int base = blockIdx.x * EBLK;

    const uint A_HI = 0, A_LO = 30720, B_HI = 61440, B_LO = 76672;
    int* sS = (int*)(sb + 91904);
    int* sD = (int*)(sb + 93440);

    for (int i = tid; i < 952; i += 256) {
        ((float4*)(sb + B_HI))[i] = ((const float4*)g_Be_hi)[i];
        ((float4*)(sb + B_LO))[i] = ((const float4*)g_Be_lo)[i];
    }
    const int use64 = g_idx64;
    for (int i = tid; i < EBLK; i += 256) {
        long long g = base + i; if (g >= E) g = E - 1;
        if (use64) {
            sS[i] = (int)((const long long*)src)[g];
            sD[i] = (int)((const long long*)dst)[g];
        } else {
            sS[i] = ((const int*)src)[g];
            sD[i] = ((const int*)dst)[g];
        }
    }

    float acc[3][NT_E][4];
#pragma unroll
    for (int mt = 0; mt < 3; mt++)
#pragma unroll
        for (int nt = 0; nt < NT_E; nt++)
#pragma unroll
            for (int r = 0; r < 4; r++) acc[mt][nt][r] = 0.0f;

#pragma unroll 1
    for (int ch = 0; ch < 4; ch++) {
        __syncthreads();
#pragma unroll
        for (int it = 0; it < 12; it++) {
            int i = it * 256 + tid;
            int m = i >> 3, k4 = (i & 7) * 4;
            int ge = base + m; if (ge >= E) ge = E - 1;
            float4 v = *(const float4*)(efeat + (size_t)ge * DIM + ch * 32 + k4);
            uint2 hi, lo; split4(v, hi, lo);
            *(uint2*)(sb + A_HI + m * 80 + k4 * 2) = hi;
            *(uint2*)(sb + A_LO + m * 80 + k4 * 2) = lo;
        }
        __syncthreads();

#pragma unroll
        for (int kt = 0; kt < 2; kt++) {
            int ktg = ch * 2 + kt;
            uint brow = ((lane >> 4) << 3) + (lane & 7);
            uint bk   = ((lane >> 3) & 1) * 16 + ktg * 32;
            uint bh4[3][4], bl4[3][4], bhT[2], blT[2];
#pragma unroll
            for (int ntp = 0; ntp < 3; ntp++) {
                uint boff = (ntp * 16 + brow) * 272 + bk;
                ldsm_x4(bh4[ntp], ub + B_HI + boff);
                ldsm_x4(bl4[ntp], ub + B_LO + boff);
            }
            {
                uint l = lane & 15;
                uint boff = (48 + (l & 7)) * 272 + ((l >> 3) & 1) * 16 + ktg * 32;
                ldsm_x2(bhT, ub + B_HI + boff);
                ldsm_x2(blT, ub + B_LO + boff);
            }
#pragma unroll
            for (int mt = 0; mt < 3; mt++) {
                uint ahi[4], alo[4];
                uint row = wid * 48 + mt * 16 + (lane & 15);
                uint off = row * 80 + (lane >> 4) * 16 + kt * 32;
                ldsm_x4(ahi, ub + A_HI + off);
                ldsm_x4(alo, ub + A_LO + off);
#pragma unroll
                for (int ntp = 0; ntp < 3; ntp++) {
                    mma16816(acc[mt][2 * ntp],     ahi, bh4[ntp]);
                    mma16816(acc[mt][2 * ntp],     alo, bh4[ntp]);
                    mma16816(acc[mt][2 * ntp],     ahi, bl4[ntp]);
                    mma16816(acc[mt][2 * ntp + 1], ahi, bh4[ntp] + 2);
                    mma16816(acc[mt][2 * ntp + 1], alo, bh4[ntp] + 2);
                    mma16816(acc[mt][2 * ntp + 1], ahi, bl4[ntp] + 2);
                }
                mma16816(acc[mt][6], ahi, bhT);
                mma16816(acc[mt][6], alo, bhT);
                mma16816(acc[mt][6], ahi, blT);
            }
        }
    }

    // frags -> sOut [384][56] f32
    __syncthreads();
    float* sOutF = (float*)sb;
#pragma unroll
    for (int mt = 0; mt < 3; mt++) {
        int r0 = wid * 48 + mt * 16 + (lane >> 2);
        int c0 = 2 * (lane & 3);
#pragma unroll
        for (int nt = 0; nt < NT_E; nt++) {
            *(float2*)(sOutF + r0 * 56 + nt * 8 + c0) =
                make_float2(acc[mt][nt][0], acc[mt][nt][1]);
            *(float2*)(sOutF + (r0 + 8) * 56 + nt * 8 + c0) =
                make_float2(acc[mt][nt][2], acc[mt][nt][3]);
        }
    }
    __syncthreads();

    // ---- widened epilogue: 13 quad-groups per row (12 x 16B + 1 x 8B) ----
    const ull* sOutU = (const ull*)sb;   // pitch 28 ull
    int rv = E - base; if (rv > EBLK) rv = EBLK;
    if (rv > 0) {
        int total = rv * 13;
#pragma unroll 2
        for (int i = tid; i < total; i += 256) {
            int row = i / 13, j = i - row * 13;
            const char* prow = (const char*)(g_P + (size_t)sS[row] * PPITCH);
            const char* qrow = (const char*)(g_Q + (size_t)sD[row] * PPITCH);
            float* orow = out + (size_t)(base + row) * NCLS;
            if (j < 12) {
                ulonglong2 p = *(const ulonglong2*)(prow + j * 16);
                ulonglong2 q = *(const ulonglong2*)(qrow + j * 16);
                const ull* so = sOutU + row * 28 + 2 * j;
                ull s0 = add2(add2(p.x, q.x), so[0]);
                ull s1 = add2(add2(p.y, q.y), so[1]);
                ((ull*)(orow + 4 * j))[0] = s0;
                ((ull*)(orow + 4 * j))[1] = s1;
            } else {
                ull p = *(const ull*)(prow + 192);
                ull q = *(const ull*)(qrow + 192);
                *(ull*)(orow + 48) = add2(add2(p, q), sOutU[row * 28 + 24]);
            }
        }
    }
}

// --------------------------------------------------------------------------
extern "C" void kernel_launch(void* const* d_in, const int* in_sizes, int n_in,
                              void* d_out, int out_size)
{
    const float* h   = (const float*)d_in[0];
    const float* e   = (const float*)d_in[1];
    const void*  src = d_in[2];
    const void*  dst = d_in[3];
    const float* W   = (const float*)d_in[4];
    const float* b   = (const float*)d_in[5];

    int N = in_sizes[0] / DIM;   // 50000
    int E = in_sizes[1] / DIM;   // 500000
    if (N > NMAX) N = NMAX;

    static int attr_done = 0;
    if (!attr_done) {
        cudaFuncSetAttribute(node_kernel, cudaFuncAttributeMaxDynamicSharedMemorySize, NODE_SMEM);
        cudaFuncSetAttribute(edge_kernel, cudaFuncAttributeMaxDynamicSharedMemorySize, EDGE_SMEM);
        attr_done = 1;
    }

    setup_kernel<<<8, 256>>>(W, src, E);
    node_kernel<<<(N + 127) / 128, 256, NODE_SMEM>>>(h, b, N);
    edge_kernel<<<(E + EBLK - 1) / EBLK, 256, EDGE_SMEM>>>(e, src, dst, (float*)d_out, E);
}

// round 14
// speedup vs baseline: 1.1779x; 1.1779x over previous
#include <cuda_runtime.h>
#include <cuda_bf16.h>
#include <cstdint>

#define DIM     128
#define NCLS    50
#define PAIRS   25
#define WPITCH  384
#define PPITCH  64
#define NMAX    50000

typedef unsigned long long ull;
typedef unsigned int uint;

__device__ float g_P[NMAX * PPITCH];
__device__ float g_Q[NMAX * PPITCH];
__device__ int   g_idx64;

// B-operand images (bf16 hi/lo, pitch 272B = 136 bf16)
__device__ __align__(16) unsigned short g_Be_hi[56 * 136];   // W3, 56 rows
__device__ __align__(16) unsigned short g_Be_lo[56 * 136];
__device__ __align__(16) unsigned short g_Bn_hi[104 * 136];  // [W1;W2]
__device__ __align__(16) unsigned short g_Bn_lo[104 * 136];

// ---------------- helpers -------------------------------------------------
__device__ __forceinline__ uint smem_u32(const void* p) {
    uint a;
    asm("{ .reg .u64 t; cvta.to.shared.u64 t, %1; cvt.u32.u64 %0, t; }"
        : "=r"(a) : "l"(p));
    return a;
}
__device__ __forceinline__ void ldsm_x4(uint r[4], uint addr) {
    asm volatile("ldmatrix.sync.aligned.m8n8.x4.shared.b16 {%0,%1,%2,%3}, [%4];"
        : "=r"(r[0]), "=r"(r[1]), "=r"(r[2]), "=r"(r[3]) : "r"(addr));
}
__device__ __forceinline__ void ldsm_x2(uint r[2], uint addr) {
    asm volatile("ldmatrix.sync.aligned.m8n8.x2.shared.b16 {%0,%1}, [%2];"
        : "=r"(r[0]), "=r"(r[1]) : "r"(addr));
}
__device__ __forceinline__ void mma16816(float* d, const uint* a, const uint* b) {
    asm volatile("mma.sync.aligned.m16n8k16.row.col.f32.bf16.bf16.f32 "
        "{%0,%1,%2,%3}, {%4,%5,%6,%7}, {%8,%9}, {%0,%1,%2,%3};"
        : "+f"(d[0]), "+f"(d[1]), "+f"(d[2]), "+f"(d[3])
        : "r"(a[0]), "r"(a[1]), "r"(a[2]), "r"(a[3]), "r"(b[0]), "r"(b[1]));
}
__device__ __forceinline__ ull add2(ull a, ull b) {
    ull d;
    asm("add.rn.f32x2 %0, %1, %2;" : "=l"(d) : "l"(a), "l"(b));
    return d;
}
__device__ __forceinline__ void split_bf16(float a, unsigned short& hi, unsigned short& lo) {
    __nv_bfloat16 bh = __float2bfloat16(a);
    float r = a - __bfloat162float(bh);
    __nv_bfloat16 bl = __float2bfloat16(r);
    hi = reinterpret_cast<unsigned short&>(bh);
    lo = reinterpret_cast<unsigned short&>(bl);
}
__device__ __forceinline__ void split4(float4 v, uint2& hi, uint2& lo) {
    uint pk0, pk1, l0, l1;
    asm("cvt.rn.bf16x2.f32 %0, %1, %2;" : "=r"(pk0) : "f"(v.y), "f"(v.x));
    asm("cvt.rn.bf16x2.f32 %0, %1, %2;" : "=r"(pk1) : "f"(v.w), "f"(v.z));
    float rx = v.x - __uint_as_float(pk0 << 16);
    float ry = v.y - __uint_as_float(pk0 & 0xffff0000u);
    float rz = v.z - __uint_as_float(pk1 << 16);
    float rw = v.w - __uint_as_float(pk1 & 0xffff0000u);
    asm("cvt.rn.bf16x2.f32 %0, %1, %2;" : "=r"(l0) : "f"(ry), "f"(rx));
    asm("cvt.rn.bf16x2.f32 %0, %1, %2;" : "=r"(l1) : "f"(rw), "f"(rz));
    hi = make_uint2(pk0, pk1);
    lo = make_uint2(l0, l1);
}

// ==========================================================================
// Setup: idx-width detect + both B images.
// ==========================================================================
__global__ void setup_kernel(const float* __restrict__ W,
                             const void* __restrict__ src, int E)
{
    int tid = threadIdx.x + blockIdx.x * blockDim.x;
    if (tid == 0) {
        const uint* a = (const uint*)src;
        int n = E < 256 ? E : 256;
        int ok = 1;
        for (int i = 0; i < n; i++)
            if (a[2 * i + 1] != 0u) { ok = 0; break; }
        g_idx64 = ok;
    }
    for (int i = tid; i < 56 * 136; i += blockDim.x * gridDim.x) {
        int n = i / 136, k = i - n * 136;
        float v = (n < NCLS && k < DIM) ? W[n * WPITCH + 2 * DIM + k] : 0.0f;
        unsigned short h, l; split_bf16(v, h, l);
        g_Be_hi[i] = h; g_Be_lo[i] = l;
    }
    for (int i = tid; i < 104 * 136; i += blockDim.x * gridDim.x) {
        int n = i / 136, k = i - n * 136;
        float v = 0.0f;
        if (k < DIM) {
            if (n < NCLS)            v = W[n * WPITCH + k];
            else if (n < 2 * NCLS)   v = W[(n - NCLS) * WPITCH + DIM + k];
        }
        unsigned short h, l; split_bf16(v, h, l);
        g_Bn_hi[i] = h; g_Bn_lo[i] = l;
    }
}

// ==========================================================================
// Node kernel (R12 best): 128 nodes/block, 256 threads, pipelined staging,
// B copied from global image, x4-paired B ldsm.
// ==========================================================================
#define NODE_SMEM 97536
#define NT_N 13

__global__ __launch_bounds__(256, 2)
void node_kernel(const float* __restrict__ h, const float* __restrict__ b, int N)
{
    extern __shared__ __align__(16) char sb[];
    const uint ub = smem_u32(sb);
    const int tid = threadIdx.x;
    const int wid = tid >> 5;
    const int lane = tid & 31;
    const int base = blockIdx.x * 128;

    const uint A_HI0 = 0, A_LO0 = 10240, A_HI1 = 20480, A_LO1 = 30720;
    const uint B_HI = 40960, B_LO = 69248;

    for (int i = tid; i < 1768; i += 256) {
        ((float4*)(sb + B_HI))[i] = ((const float4*)g_Bn_hi)[i];
        ((float4*)(sb + B_LO))[i] = ((const float4*)g_Bn_lo)[i];
    }

    float acc[NT_N][4];
#pragma unroll
    for (int nt = 0; nt < NT_N; nt++)
#pragma unroll
        for (int r = 0; r < 4; r++) acc[nt][r] = 0.0f;

    int pm[4], pk[4], gn[4];
#pragma unroll
    for (int it = 0; it < 4; it++) {
        int i = it * 256 + tid;
        pm[it] = i >> 3; pk[it] = (i & 7) * 4;
        int g = base + pm[it]; if (g >= N) g = N - 1;
        gn[it] = g;
    }

    float4 pf[4];
#pragma unroll
    for (int it = 0; it < 4; it++)
        pf[it] = *(const float4*)(h + (size_t)gn[it] * DIM + pk[it]);
#pragma unroll
    for (int it = 0; it < 4; it++) {
        uint2 hi, lo; split4(pf[it], hi, lo);
        *(uint2*)(sb + A_HI0 + pm[it] * 80 + pk[it] * 2) = hi;
        *(uint2*)(sb + A_LO0 + pm[it] * 80 + pk[it] * 2) = lo;
    }
#pragma unroll
    for (int it = 0; it < 4; it++)
        pf[it] = *(const float4*)(h + (size_t)gn[it] * DIM + 32 + pk[it]);
    __syncthreads();

#pragma unroll
    for (int ch = 0; ch < 4; ch++) {
        if (ch < 3) {
            const uint nh = (ch & 1) ? A_HI0 : A_HI1;
            const uint nl = (ch & 1) ? A_LO0 : A_LO1;
#pragma unroll
            for (int it = 0; it < 4; it++) {
                uint2 hi, lo; split4(pf[it], hi, lo);
                *(uint2*)(sb + nh + pm[it] * 80 + pk[it] * 2) = hi;
                *(uint2*)(sb + nl + pm[it] * 80 + pk[it] * 2) = lo;
            }
            if (ch < 2) {
#pragma unroll
                for (int it = 0; it < 4; it++)
                    pf[it] = *(const float4*)(h + (size_t)gn[it] * DIM
                                              + (ch + 2) * 32 + pk[it]);
            }
        }
        const uint AH = (ch & 1) ? A_HI1 : A_HI0;
        const uint AL = (ch & 1) ? A_LO1 : A_LO0;
#pragma unroll
        for (int kt = 0; kt < 2; kt++) {
            int ktg = ch * 2 + kt;
            uint ahi[4], alo[4];
            uint row = wid * 16 + (lane & 15);
            uint off = row * 80 + (lane >> 4) * 16 + kt * 32;
            ldsm_x4(ahi, ub + AH + off);
            ldsm_x4(alo, ub + AL + off);
            uint brow = ((lane >> 4) << 3) + (lane & 7);
            uint bk   = ((lane >> 3) & 1) * 16 + ktg * 32;
#pragma unroll
            for (int ntp = 0; ntp < 6; ntp++) {
                uint boff = (ntp * 16 + brow) * 272 + bk;
                uint bh4[4], bl4[4];
                ldsm_x4(bh4, ub + B_HI + boff);
                ldsm_x4(bl4, ub + B_LO + boff);
                mma16816(acc[2 * ntp],     ahi, bh4);
                mma16816(acc[2 * ntp],     alo, bh4);
                mma16816(acc[2 * ntp],     ahi, bl4);
                mma16816(acc[2 * ntp + 1], ahi, bh4 + 2);
                mma16816(acc[2 * ntp + 1], alo, bh4 + 2);
                mma16816(acc[2 * ntp + 1], ahi, bl4 + 2);
            }
            {
                uint l = lane & 15;
                uint boff = (96 + (l & 7)) * 272 + ((l >> 3) & 1) * 16 + ktg * 32;
                uint bhi[2], blo[2];
                ldsm_x2(bhi, ub + B_HI + boff);
                ldsm_x2(blo, ub + B_LO + boff);
                mma16816(acc[12], ahi, bhi);
                mma16816(acc[12], alo, bhi);
                mma16816(acc[12], ahi, blo);
            }
        }
        __syncthreads();
    }

    float* sOutF = (float*)sb;
    {
        int r0 = wid * 16 + (lane >> 2);
        int c0 = 2 * (lane & 3);
#pragma unroll
        for (int nt = 0; nt < NT_N; nt++) {
            *(float2*)(sOutF + r0 * 104 + nt * 8 + c0) =
                make_float2(acc[nt][0], acc[nt][1]);
            *(float2*)(sOutF + (r0 + 8) * 104 + nt * 8 + c0) =
                make_float2(acc[nt][2], acc[nt][3]);
        }
    }
    __syncthreads();

    const ull* sOutU = (const ull*)sb;   // pitch 52 ull
    const ull* b2 = (const ull*)b;
    int rv = N - base; if (rv > 128) rv = 128;
    if (rv > 0) {
        for (int i = tid; i < rv * PAIRS; i += 256) {
            int m = i / PAIRS, c = i - m * PAIRS;
            *(ull*)(g_P + (size_t)(base + m) * PPITCH + 2 * c) =
                add2(sOutU[m * 52 + c], b2[c]);
            *(ull*)(g_Q + (size_t)(base + m) * PPITCH + 2 * c) =
                sOutU[m * 52 + 25 + c];
        }
    }
}

// ==========================================================================
// Edge kernel (R8 best config): 256 edges/block, 256 threads
// (8 warps x 2 m-tiles of 16), x2 B ldsm, unconstrained regs (2 blk/SM).
// smem: A_HI @0 (20480), A_LO @20480, B_HI @40960 (15232), B_LO @56192,
//       sS @71424, sD @72448 -> 73472. sOut overlays @0: 256x56 f32.
// Adds: L2 prefetch of P/Q rows after index load.
// ==========================================================================
#define EDGE_SMEM 73472
#define NT_E 7

__global__ __launch_bounds__(256, 2)
void edge_kernel(const float* __restrict__ efeat,
                 const void* __restrict__ src,
                 const void* __restrict__ dst,
                 float* __restrict__ out, int E)
{
    extern __shared__ __align__(16) char sb[];
    const uint ub = smem_u32(sb);
    const int tid = threadIdx.x;
    const int wid = tid >> 5;
    const int lane = tid & 31;
    const int base = blockIdx.x * 256;

    const uint A_HI = 0, A_LO = 20480, B_HI = 40960, B_LO = 56192;
    int* sS = (int*)(sb + 71424);
    int* sD = (int*)(sb + 72448);

    for (int i = tid; i < 952; i += 256) {
        ((float4*)(sb + B_HI))[i] = ((const float4*)g_Be_hi)[i];
        ((float4*)(sb + B_LO))[i] = ((const float4*)g_Be_lo)[i];
    }
    const int use64 = g_idx64;
    {
        long long g = base + tid; if (g >= E) g = E - 1;
        int s, d;
        if (use64) {
            s = (int)((const long long*)src)[g];
            d = (int)((const long long*)dst)[g];
        } else {
            s = ((const int*)src)[g];
            d = ((const int*)dst)[g];
        }
        sS[tid] = s; sD[tid] = d;
        // warm L2 for the epilogue gather (200B rows; touch both 128B lines)
        const char* pp = (const char*)(g_P + (size_t)s * PPITCH);
        const char* qq = (const char*)(g_Q + (size_t)d * PPITCH);
        asm volatile("prefetch.global.L2 [%0];" :: "l"(pp));
        asm volatile("prefetch.global.L2 [%0];" :: "l"(pp + 128));
        asm volatile("prefetch.global.L2 [%0];" :: "l"(qq));
        asm volatile("prefetch.global.L2 [%0];" :: "l"(qq + 128));
    }

    float acc[2][NT_E][4];
#pragma unroll
    for (int mt = 0; mt < 2; mt++)
#pragma unroll
        for (int nt = 0; nt < NT_E; nt++)
#pragma unroll
            for (int r = 0; r < 4; r++) acc[mt][nt][r] = 0.0f;

#pragma unroll 1
    for (int ch = 0; ch < 4; ch++) {
        __syncthreads();
        // stage A chunk: 256 edges x 32 k (2048 float4)
#pragma unroll
        for (int it = 0; it < 8; it++) {
            int i = it * 256 + tid;
            int m = i >> 3, k4 = (i & 7) * 4;
            int ge = base + m; if (ge >= E) ge = E - 1;
            float4 v = *(const float4*)(efeat + (size_t)ge * DIM + ch * 32 + k4);
            uint2 hi, lo; split4(v, hi, lo);
            *(uint2*)(sb + A_HI + m * 80 + k4 * 2) = hi;
            *(uint2*)(sb + A_LO + m * 80 + k4 * 2) = lo;
        }
        __syncthreads();

#pragma unroll
        for (int kt = 0; kt < 2; kt++) {
            int ktg = ch * 2 + kt;
            uint ahi[2][4], alo[2][4];
#pragma unroll
            for (int mt = 0; mt < 2; mt++) {
                uint row = wid * 32 + mt * 16 + (lane & 15);
                uint off = row * 80 + (lane >> 4) * 16 + kt * 32;
                ldsm_x4(ahi[mt], ub + A_HI + off);
                ldsm_x4(alo[mt], ub + A_LO + off);
            }
#pragma unroll
            for (int nt = 0; nt < NT_E; nt++) {
                uint l = lane & 15;
                uint boff = (nt * 8 + (l & 7)) * 272 + ((l >> 3) & 1) * 16 + ktg * 32;
                uint bhi[2], blo[2];
                ldsm_x2(bhi, ub + B_HI + boff);
                ldsm_x2(blo, ub + B_LO + boff);
#pragma unroll
                for (int mt = 0; mt < 2; mt++) {
                    mma16816(acc[mt][nt], ahi[mt], bhi);
                    mma16816(acc[mt][nt], alo[mt], bhi);
                    mma16816(acc[mt][nt], ahi[mt], blo);
                }
            }
        }
    }

    // frags -> sOut [256][56] f32
    __syncthreads();
    float* sOutF = (float*)sb;
#pragma unroll
    for (int mt = 0; mt < 2; mt++) {
        int r0 = wid * 32 + mt * 16 + (lane >> 2);
        int c0 = 2 * (lane & 3);
#pragma unroll
        for (int nt = 0; nt < NT_E; nt++) {
            *(float2*)(sOutF + r0 * 56 + nt * 8 + c0) =
                make_float2(acc[mt][nt][0], acc[mt][nt][1]);
            *(float2*)(sOutF + (r0 + 8) * 56 + nt * 8 + c0) =
                make_float2(acc[mt][nt][2], acc[mt][nt][3]);
        }
    }
    __syncthreads();

    const ull* sOutU = (const ull*)sb;   // pitch 28 ull
    int rv = E - base; if (rv > 256) rv = 256;
    if (rv > 0) {
        for (int i = tid; i < rv * PAIRS; i += 256) {
            int row = i / PAIRS, c = i - row * PAIRS;
            ull pv = *(const ull*)(g_P + (size_t)sS[row] * PPITCH + 2 * c);
            ull qv = *(const ull*)(g_Q + (size_t)sD[row] * PPITCH + 2 * c);
            *(ull*)(out + (size_t)(base + row) * NCLS + 2 * c) =
                add2(add2(pv, qv), sOutU[row * 28 + c]);
        }
    }
}

// --------------------------------------------------------------------------
extern "C" void kernel_launch(void* const* d_in, const int* in_sizes, int n_in,
                              void* d_out, int out_size)
{
    const float* h   = (const float*)d_in[0];
    const float* e   = (const float*)d_in[1];
    const void*  src = d_in[2];
    const void*  dst = d_in[3];
    const float* W   = (const float*)d_in[4];
    const float* b   = (const float*)d_in[5];

    int N = in_sizes[0] / DIM;   // 50000
    int E = in_sizes[1] / DIM;   // 500000
    if (N > NMAX) N = NMAX;

    static int attr_done = 0;
    if (!attr_done) {
        cudaFuncSetAttribute(node_kernel, cudaFuncAttributeMaxDynamicSharedMemorySize, NODE_SMEM);
        cudaFuncSetAttribute(edge_kernel, cudaFuncAttributeMaxDynamicSharedMemorySize, EDGE_SMEM);
        attr_done = 1;
    }

    setup_kernel<<<64, 256>>>(W, src, E);
    node_kernel<<<(N + 127) / 128, 256, NODE_SMEM>>>(h, b, N);
    edge_kernel<<<(E + 255) / 256, 256, EDGE_SMEM>>>(e, src, dst, (float*)d_out, E);
}

// round 15
// speedup vs baseline: 1.2923x; 1.0971x over previous
#include <cuda_runtime.h>
#include <cuda_bf16.h>
#include <cstdint>

#define DIM     128
#define NCLS    50
#define PAIRS   25
#define WPITCH  384
#define PPITCH  64
#define NMAX    50000

typedef unsigned long long ull;
typedef unsigned int uint;

__device__ float g_P[NMAX * PPITCH];
__device__ float g_Q[NMAX * PPITCH];
__device__ int   g_idx64;

// B-operand images (bf16 hi/lo, pitch 272B = 136 bf16)
__device__ __align__(16) unsigned short g_Be_hi[56 * 136];   // W3, 56 rows
__device__ __align__(16) unsigned short g_Be_lo[56 * 136];
__device__ __align__(16) unsigned short g_Bn_hi[104 * 136];  // [W1;W2]
__device__ __align__(16) unsigned short g_Bn_lo[104 * 136];

// ---------------- helpers -------------------------------------------------
__device__ __forceinline__ uint smem_u32(const void* p) {
    uint a;
    asm("{ .reg .u64 t; cvta.to.shared.u64 t, %1; cvt.u32.u64 %0, t; }"
        : "=r"(a) : "l"(p));
    return a;
}
__device__ __forceinline__ void ldsm_x4(uint r[4], uint addr) {
    asm volatile("ldmatrix.sync.aligned.m8n8.x4.shared.b16 {%0,%1,%2,%3}, [%4];"
        : "=r"(r[0]), "=r"(r[1]), "=r"(r[2]), "=r"(r[3]) : "r"(addr));
}
__device__ __forceinline__ void ldsm_x2(uint r[2], uint addr) {
    asm volatile("ldmatrix.sync.aligned.m8n8.x2.shared.b16 {%0,%1}, [%2];"
        : "=r"(r[0]), "=r"(r[1]) : "r"(addr));
}
__device__ __forceinline__ void mma16816(float* d, const uint* a, const uint* b) {
    asm volatile("mma.sync.aligned.m16n8k16.row.col.f32.bf16.bf16.f32 "
        "{%0,%1,%2,%3}, {%4,%5,%6,%7}, {%8,%9}, {%0,%1,%2,%3};"
        : "+f"(d[0]), "+f"(d[1]), "+f"(d[2]), "+f"(d[3])
        : "r"(a[0]), "r"(a[1]), "r"(a[2]), "r"(a[3]), "r"(b[0]), "r"(b[1]));
}
__device__ __forceinline__ ull add2(ull a, ull b) {
    ull d;
    asm("add.rn.f32x2 %0, %1, %2;" : "=l"(d) : "l"(a), "l"(b));
    return d;
}
__device__ __forceinline__ void split_bf16(float a, unsigned short& hi, unsigned short& lo) {
    __nv_bfloat16 bh = __float2bfloat16(a);
    float r = a - __bfloat162float(bh);
    __nv_bfloat16 bl = __float2bfloat16(r);
    hi = reinterpret_cast<unsigned short&>(bh);
    lo = reinterpret_cast<unsigned short&>(bl);
}
__device__ __forceinline__ void split4(float4 v, uint2& hi, uint2& lo) {
    uint pk0, pk1, l0, l1;
    asm("cvt.rn.bf16x2.f32 %0, %1, %2;" : "=r"(pk0) : "f"(v.y), "f"(v.x));
    asm("cvt.rn.bf16x2.f32 %0, %1, %2;" : "=r"(pk1) : "f"(v.w), "f"(v.z));
    float rx = v.x - __uint_as_float(pk0 << 16);
    float ry = v.y - __uint_as_float(pk0 & 0xffff0000u);
    float rz = v.z - __uint_as_float(pk1 << 16);
    float rw = v.w - __uint_as_float(pk1 & 0xffff0000u);
    asm("cvt.rn.bf16x2.f32 %0, %1, %2;" : "=r"(l0) : "f"(ry), "f"(rx));
    asm("cvt.rn.bf16x2.f32 %0, %1, %2;" : "=r"(l1) : "f"(rw), "f"(rz));
    hi = make_uint2(pk0, pk1);
    lo = make_uint2(l0, l1);
}

// ==========================================================================
// Setup: idx-width detect + both B images.
// ==========================================================================
__global__ void setup_kernel(const float* __restrict__ W,
                             const void* __restrict__ src, int E)
{
    int tid = threadIdx.x + blockIdx.x * blockDim.x;
    if (tid == 0) {
        const uint* a = (const uint*)src;
        int n = E < 256 ? E : 256;
        int ok = 1;
        for (int i = 0; i < n; i++)
            if (a[2 * i + 1] != 0u) { ok = 0; break; }
        g_idx64 = ok;
    }
    for (int i = tid; i < 56 * 136; i += blockDim.x * gridDim.x) {
        int n = i / 136, k = i - n * 136;
        float v = (n < NCLS && k < DIM) ? W[n * WPITCH + 2 * DIM + k] : 0.0f;
        unsigned short h, l; split_bf16(v, h, l);
        g_Be_hi[i] = h; g_Be_lo[i] = l;
    }
    for (int i = tid; i < 104 * 136; i += blockDim.x * gridDim.x) {
        int n = i / 136, k = i - n * 136;
        float v = 0.0f;
        if (k < DIM) {
            if (n < NCLS)            v = W[n * WPITCH + k];
            else if (n < 2 * NCLS)   v = W[(n - NCLS) * WPITCH + DIM + k];
        }
        unsigned short h, l; split_bf16(v, h, l);
        g_Bn_hi[i] = h; g_Bn_lo[i] = l;
    }
}

// ==========================================================================
// Node kernel (unchanged best): 128 nodes/block, 256 threads, pipelined,
// B copied from global image, x4-paired B ldsm.
// ==========================================================================
#define NODE_SMEM 97536
#define NT_N 13

__global__ __launch_bounds__(256, 2)
void node_kernel(const float* __restrict__ h, const float* __restrict__ b, int N)
{
    extern __shared__ __align__(16) char sb[];
    const uint ub = smem_u32(sb);
    const int tid = threadIdx.x;
    const int wid = tid >> 5;
    const int lane = tid & 31;
    const int base = blockIdx.x * 128;

    const uint A_HI0 = 0, A_LO0 = 10240, A_HI1 = 20480, A_LO1 = 30720;
    const uint B_HI = 40960, B_LO = 69248;

    for (int i = tid; i < 1768; i += 256) {
        ((float4*)(sb + B_HI))[i] = ((const float4*)g_Bn_hi)[i];
        ((float4*)(sb + B_LO))[i] = ((const float4*)g_Bn_lo)[i];
    }

    float acc[NT_N][4];
#pragma unroll
    for (int nt = 0; nt < NT_N; nt++)
#pragma unroll
        for (int r = 0; r < 4; r++) acc[nt][r] = 0.0f;

    int pm[4], pk[4], gn[4];
#pragma unroll
    for (int it = 0; it < 4; it++) {
        int i = it * 256 + tid;
        pm[it] = i >> 3; pk[it] = (i & 7) * 4;
        int g = base + pm[it]; if (g >= N) g = N - 1;
        gn[it] = g;
    }

    float4 pf[4];
#pragma unroll
    for (int it = 0; it < 4; it++)
        pf[it] = *(const float4*)(h + (size_t)gn[it] * DIM + pk[it]);
#pragma unroll
    for (int it = 0; it < 4; it++) {
        uint2 hi, lo; split4(pf[it], hi, lo);
        *(uint2*)(sb + A_HI0 + pm[it] * 80 + pk[it] * 2) = hi;
        *(uint2*)(sb + A_LO0 + pm[it] * 80 + pk[it] * 2) = lo;
    }
#pragma unroll
    for (int it = 0; it < 4; it++)
        pf[it] = *(const float4*)(h + (size_t)gn[it] * DIM + 32 + pk[it]);
    __syncthreads();

#pragma unroll
    for (int ch = 0; ch < 4; ch++) {
        if (ch < 3) {
            const uint nh = (ch & 1) ? A_HI0 : A_HI1;
            const uint nl = (ch & 1) ? A_LO0 : A_LO1;
#pragma unroll
            for (int it = 0; it < 4; it++) {
                uint2 hi, lo; split4(pf[it], hi, lo);
                *(uint2*)(sb + nh + pm[it] * 80 + pk[it] * 2) = hi;
                *(uint2*)(sb + nl + pm[it] * 80 + pk[it] * 2) = lo;
            }
            if (ch < 2) {
#pragma unroll
                for (int it = 0; it < 4; it++)
                    pf[it] = *(const float4*)(h + (size_t)gn[it] * DIM
                                              + (ch + 2) * 32 + pk[it]);
            }
        }
        const uint AH = (ch & 1) ? A_HI1 : A_HI0;
        const uint AL = (ch & 1) ? A_LO1 : A_LO0;
#pragma unroll
        for (int kt = 0; kt < 2; kt++) {
            int ktg = ch * 2 + kt;
            uint ahi[4], alo[4];
            uint row = wid * 16 + (lane & 15);
            uint off = row * 80 + (lane >> 4) * 16 + kt * 32;
            ldsm_x4(ahi, ub + AH + off);
            ldsm_x4(alo, ub + AL + off);
            uint brow = ((lane >> 4) << 3) + (lane & 7);
            uint bk   = ((lane >> 3) & 1) * 16 + ktg * 32;
#pragma unroll
            for (int ntp = 0; ntp < 6; ntp++) {
                uint boff = (ntp * 16 + brow) * 272 + bk;
                uint bh4[4], bl4[4];
                ldsm_x4(bh4, ub + B_HI + boff);
                ldsm_x4(bl4, ub + B_LO + boff);
                mma16816(acc[2 * ntp],     ahi, bh4);
                mma16816(acc[2 * ntp],     alo, bh4);
                mma16816(acc[2 * ntp],     ahi, bl4);
                mma16816(acc[2 * ntp + 1], ahi, bh4 + 2);
                mma16816(acc[2 * ntp + 1], alo, bh4 + 2);
                mma16816(acc[2 * ntp + 1], ahi, bl4 + 2);
            }
            {
                uint l = lane & 15;
                uint boff = (96 + (l & 7)) * 272 + ((l >> 3) & 1) * 16 + ktg * 32;
                uint bhi[2], blo[2];
                ldsm_x2(bhi, ub + B_HI + boff);
                ldsm_x2(blo, ub + B_LO + boff);
                mma16816(acc[12], ahi, bhi);
                mma16816(acc[12], alo, bhi);
                mma16816(acc[12], ahi, blo);
            }
        }
        __syncthreads();
    }

    float* sOutF = (float*)sb;
    {
        int r0 = wid * 16 + (lane >> 2);
        int c0 = 2 * (lane & 3);
#pragma unroll
        for (int nt = 0; nt < NT_N; nt++) {
            *(float2*)(sOutF + r0 * 104 + nt * 8 + c0) =
                make_float2(acc[nt][0], acc[nt][1]);
            *(float2*)(sOutF + (r0 + 8) * 104 + nt * 8 + c0) =
                make_float2(acc[nt][2], acc[nt][3]);
        }
    }
    __syncthreads();

    const ull* sOutU = (const ull*)sb;   // pitch 52 ull
    const ull* b2 = (const ull*)b;
    int rv = N - base; if (rv > 128) rv = 128;
    if (rv > 0) {
        for (int i = tid; i < rv * PAIRS; i += 256) {
            int m = i / PAIRS, c = i - m * PAIRS;
            *(ull*)(g_P + (size_t)(base + m) * PPITCH + 2 * c) =
                add2(sOutU[m * 52 + c], b2[c]);
            *(ull*)(g_Q + (size_t)(base + m) * PPITCH + 2 * c) =
                sOutU[m * 52 + 25 + c];
        }
    }
}

// ==========================================================================
// Edge kernel: 256 edges/block, 256 threads (8 warps x 2 m-tiles),
// PIPELINED: 8 chunks of K=16, double-buffered A (pitch 48), 1 sync/chunk.
// smem: A_HI0 @0 (12288), A_LO0 @12288, A_HI1 @24576, A_LO1 @36864,
//       B_HI @49152 (15232), B_LO @64384 (15232),
//       sS @79616 (1024), sD @80640 (1024) -> 81664.  2 blocks/SM.
// sOut overlays @0: 256x56 f32 = 57344.
// ==========================================================================
#define EDGE_SMEM 81664
#define NT_E 7

__global__ __launch_bounds__(256, 2)
void edge_kernel(const float* __restrict__ efeat,
                 const void* __restrict__ src,
                 const void* __restrict__ dst,
                 float* __restrict__ out, int E)
{
    extern __shared__ __align__(16) char sb[];
    const uint ub = smem_u32(sb);
    const int tid = threadIdx.x;
    const int wid = tid >> 5;
    const int lane = tid & 31;
    const int base = blockIdx.x * 256;

    const uint A_HI0 = 0, A_LO0 = 12288, A_HI1 = 24576, A_LO1 = 36864;
    const uint B_HI = 49152, B_LO = 64384;
    int* sS = (int*)(sb + 79616);
    int* sD = (int*)(sb + 80640);

    for (int i = tid; i < 952; i += 256) {
        ((float4*)(sb + B_HI))[i] = ((const float4*)g_Be_hi)[i];
        ((float4*)(sb + B_LO))[i] = ((const float4*)g_Be_lo)[i];
    }
    const int use64 = g_idx64;
    {
        long long g = base + tid; if (g >= E) g = E - 1;
        int s, d;
        if (use64) {
            s = (int)((const long long*)src)[g];
            d = (int)((const long long*)dst)[g];
        } else {
            s = ((const int*)src)[g];
            d = ((const int*)dst)[g];
        }
        sS[tid] = s; sD[tid] = d;
        const char* pp = (const char*)(g_P + (size_t)s * PPITCH);
        const char* qq = (const char*)(g_Q + (size_t)d * PPITCH);
        asm volatile("prefetch.global.L2 [%0];" :: "l"(pp));
        asm volatile("prefetch.global.L2 [%0];" :: "l"(pp + 128));
        asm volatile("prefetch.global.L2 [%0];" :: "l"(qq));
        asm volatile("prefetch.global.L2 [%0];" :: "l"(qq + 128));
    }

    float acc[2][NT_E][4];
#pragma unroll
    for (int mt = 0; mt < 2; mt++)
#pragma unroll
        for (int nt = 0; nt < NT_E; nt++)
#pragma unroll
            for (int r = 0; r < 4; r++) acc[mt][nt][r] = 0.0f;

    // staging coords: per chunk 256 edges x 16 k = 1024 float4, 4 per thread
    int pm[4], pk[4]; long long ge[4];
#pragma unroll
    for (int it = 0; it < 4; it++) {
        int i = it * 256 + tid;
        pm[it] = i >> 2; pk[it] = (i & 3) * 4;
        long long g = base + pm[it]; if (g >= E) g = E - 1;
        ge[it] = g;
    }

    float4 pf[4];
    // prefetch chunk 0 and store to buf0
#pragma unroll
    for (int it = 0; it < 4; it++)
        pf[it] = *(const float4*)(efeat + (size_t)ge[it] * DIM + pk[it]);
#pragma unroll
    for (int it = 0; it < 4; it++) {
        uint2 hi, lo; split4(pf[it], hi, lo);
        *(uint2*)(sb + A_HI0 + pm[it] * 48 + pk[it] * 2) = hi;
        *(uint2*)(sb + A_LO0 + pm[it] * 48 + pk[it] * 2) = lo;
    }
    // prefetch chunk 1
#pragma unroll
    for (int it = 0; it < 4; it++)
        pf[it] = *(const float4*)(efeat + (size_t)ge[it] * DIM + 16 + pk[it]);
    __syncthreads();

#pragma unroll
    for (int ch = 0; ch < 8; ch++) {
        if (ch < 7) {
            const uint nh = (ch & 1) ? A_HI0 : A_HI1;
            const uint nl = (ch & 1) ? A_LO0 : A_LO1;
#pragma unroll
            for (int it = 0; it < 4; it++) {
                uint2 hi, lo; split4(pf[it], hi, lo);
                *(uint2*)(sb + nh + pm[it] * 48 + pk[it] * 2) = hi;
                *(uint2*)(sb + nl + pm[it] * 48 + pk[it] * 2) = lo;
            }
            if (ch < 6) {
#pragma unroll
                for (int it = 0; it < 4; it++)
                    pf[it] = *(const float4*)(efeat + (size_t)ge[it] * DIM
                                              + (ch + 2) * 16 + pk[it]);
            }
        }
        const uint AH = (ch & 1) ? A_HI1 : A_HI0;
        const uint AL = (ch & 1) ? A_LO1 : A_LO0;

        uint ahi[2][4], alo[2][4];
#pragma unroll
        for (int mt = 0; mt < 2; mt++) {
            uint row = wid * 32 + mt * 16 + (lane & 15);
            uint off = row * 48 + (lane >> 4) * 16;
            ldsm_x4(ahi[mt], ub + AH + off);
            ldsm_x4(alo[mt], ub + AL + off);
        }
#pragma unroll
        for (int nt = 0; nt < NT_E; nt++) {
            uint l = lane & 15;
            uint boff = (nt * 8 + (l & 7)) * 272 + ((l >> 3) & 1) * 16 + ch * 32;
            uint bhi[2], blo[2];
            ldsm_x2(bhi, ub + B_HI + boff);
            ldsm_x2(blo, ub + B_LO + boff);
#pragma unroll
            for (int mt = 0; mt < 2; mt++) {
                mma16816(acc[mt][nt], ahi[mt], bhi);
                mma16816(acc[mt][nt], alo[mt], bhi);
                mma16816(acc[mt][nt], ahi[mt], blo);
            }
        }
        __syncthreads();
    }

    // frags -> sOut [256][56] f32
    float* sOutF = (float*)sb;
#pragma unroll
    for (int mt = 0; mt < 2; mt++) {
        int r0 = wid * 32 + mt * 16 + (lane >> 2);
        int c0 = 2 * (lane & 3);
#pragma unroll
        for (int nt = 0; nt < NT_E; nt++) {
            *(float2*)(sOutF + r0 * 56 + nt * 8 + c0) =
                make_float2(acc[mt][nt][0], acc[mt][nt][1]);
            *(float2*)(sOutF + (r0 + 8) * 56 + nt * 8 + c0) =
                make_float2(acc[mt][nt][2], acc[mt][nt][3]);
        }
    }
    __syncthreads();

    const ull* sOutU = (const ull*)sb;   // pitch 28 ull
    int rv = E - base; if (rv > 256) rv = 256;
    if (rv > 0) {
        for (int i = tid; i < rv * PAIRS; i += 256) {
            int row = i / PAIRS, c = i - row * PAIRS;
            ull pv = *(const ull*)(g_P + (size_t)sS[row] * PPITCH + 2 * c);
            ull qv = *(const ull*)(g_Q + (size_t)sD[row] * PPITCH + 2 * c);
            *(ull*)(out + (size_t)(base + row) * NCLS + 2 * c) =
                add2(add2(pv, qv), sOutU[row * 28 + c]);
        }
    }
}

// --------------------------------------------------------------------------
extern "C" void kernel_launch(void* const* d_in, const int* in_sizes, int n_in,
                              void* d_out, int out_size)
{
    const float* h   = (const float*)d_in[0];
    const float* e   = (const float*)d_in[1];
    const void*  src = d_in[2];
    const void*  dst = d_in[3];
    const float* W   = (const float*)d_in[4];
    const float* b   = (const float*)d_in[5];

    int N = in_sizes[0] / DIM;   // 50000
    int E = in_sizes[1] / DIM;   // 500000
    if (N > NMAX) N = NMAX;

    static int attr_done = 0;
    if (!attr_done) {
        cudaFuncSetAttribute(node_kernel, cudaFuncAttributeMaxDynamicSharedMemorySize, NODE_SMEM);
        cudaFuncSetAttribute(edge_kernel, cudaFuncAttributeMaxDynamicSharedMemorySize, EDGE_SMEM);
        attr_done = 1;
    }

    setup_kernel<<<64, 256>>>(W, src, E);
    node_kernel<<<(N + 127) / 128, 256, NODE_SMEM>>>(h, b, N);
    edge_kernel<<<(E + 255) / 256, 256, EDGE_SMEM>>>(e, src, dst, (float*)d_out, E);
}

// round 16
// speedup vs baseline: 1.3116x; 1.0149x over previous
#include <cuda_runtime.h>
#include <cuda_bf16.h>
#include <cstdint>

#define DIM     128
#define NCLS    50
#define PAIRS   25
#define WPITCH  384
#define PPITCH  64
#define NMAX    50000

typedef unsigned long long ull;
typedef unsigned int uint;

__device__ float g_P[NMAX * PPITCH];
__device__ float g_Q[NMAX * PPITCH];
__device__ int   g_idx64;

// B-operand images (bf16 hi/lo, pitch 272B = 136 bf16)
__device__ __align__(16) unsigned short g_Be_hi[56 * 136];   // W3, 56 rows
__device__ __align__(16) unsigned short g_Be_lo[56 * 136];
__device__ __align__(16) unsigned short g_Bn_hi[104 * 136];  // [W1;W2]
__device__ __align__(16) unsigned short g_Bn_lo[104 * 136];

// ---------------- helpers -------------------------------------------------
__device__ __forceinline__ uint smem_u32(const void* p) {
    uint a;
    asm("{ .reg .u64 t; cvta.to.shared.u64 t, %1; cvt.u32.u64 %0, t; }"
        : "=r"(a) : "l"(p));
    return a;
}
__device__ __forceinline__ void ldsm_x4(uint r[4], uint addr) {
    asm volatile("ldmatrix.sync.aligned.m8n8.x4.shared.b16 {%0,%1,%2,%3}, [%4];"
        : "=r"(r[0]), "=r"(r[1]), "=r"(r[2]), "=r"(r[3]) : "r"(addr));
}
__device__ __forceinline__ void ldsm_x2(uint r[2], uint addr) {
    asm volatile("ldmatrix.sync.aligned.m8n8.x2.shared.b16 {%0,%1}, [%2];"
        : "=r"(r[0]), "=r"(r[1]) : "r"(addr));
}
__device__ __forceinline__ void mma16816(float* d, const uint* a, const uint* b) {
    asm volatile("mma.sync.aligned.m16n8k16.row.col.f32.bf16.bf16.f32 "
        "{%0,%1,%2,%3}, {%4,%5,%6,%7}, {%8,%9}, {%0,%1,%2,%3};"
        : "+f"(d[0]), "+f"(d[1]), "+f"(d[2]), "+f"(d[3])
        : "r"(a[0]), "r"(a[1]), "r"(a[2]), "r"(a[3]), "r"(b[0]), "r"(b[1]));
}
__device__ __forceinline__ ull add2(ull a, ull b) {
    ull d;
    asm("add.rn.f32x2 %0, %1, %2;" : "=l"(d) : "l"(a), "l"(b));
    return d;
}
__device__ __forceinline__ void split_bf16(float a, unsigned short& hi, unsigned short& lo) {
    __nv_bfloat16 bh = __float2bfloat16(a);
    float r = a - __bfloat162float(bh);
    __nv_bfloat16 bl = __float2bfloat16(r);
    hi = reinterpret_cast<unsigned short&>(bh);
    lo = reinterpret_cast<unsigned short&>(bl);
}
__device__ __forceinline__ void split4(float4 v, uint2& hi, uint2& lo) {
    uint pk0, pk1, l0, l1;
    asm("cvt.rn.bf16x2.f32 %0, %1, %2;" : "=r"(pk0) : "f"(v.y), "f"(v.x));
    asm("cvt.rn.bf16x2.f32 %0, %1, %2;" : "=r"(pk1) : "f"(v.w), "f"(v.z));
    float rx = v.x - __uint_as_float(pk0 << 16);
    float ry = v.y - __uint_as_float(pk0 & 0xffff0000u);
    float rz = v.z - __uint_as_float(pk1 << 16);
    float rw = v.w - __uint_as_float(pk1 & 0xffff0000u);
    asm("cvt.rn.bf16x2.f32 %0, %1, %2;" : "=r"(l0) : "f"(ry), "f"(rx));
    asm("cvt.rn.bf16x2.f32 %0, %1, %2;" : "=r"(l1) : "f"(rw), "f"(rz));
    hi = make_uint2(pk0, pk1);
    lo = make_uint2(l0, l1);
}

// ==========================================================================
// Setup: idx-width detect + both B images.
// ==========================================================================
__global__ void setup_kernel(const float* __restrict__ W,
                             const void* __restrict__ src, int E)
{
    int tid = threadIdx.x + blockIdx.x * blockDim.x;
    if (tid == 0) {
        const uint* a = (const uint*)src;
        int n = E < 256 ? E : 256;
        int ok = 1;
        for (int i = 0; i < n; i++)
            if (a[2 * i + 1] != 0u) { ok = 0; break; }
        g_idx64 = ok;
    }
    for (int i = tid; i < 56 * 136; i += blockDim.x * gridDim.x) {
        int n = i / 136, k = i - n * 136;
        float v = (n < NCLS && k < DIM) ? W[n * WPITCH + 2 * DIM + k] : 0.0f;
        unsigned short h, l; split_bf16(v, h, l);
        g_Be_hi[i] = h; g_Be_lo[i] = l;
    }
    for (int i = tid; i < 104 * 136; i += blockDim.x * gridDim.x) {
        int n = i / 136, k = i - n * 136;
        float v = 0.0f;
        if (k < DIM) {
            if (n < NCLS)            v = W[n * WPITCH + k];
            else if (n < 2 * NCLS)   v = W[(n - NCLS) * WPITCH + DIM + k];
        }
        unsigned short h, l; split_bf16(v, h, l);
        g_Bn_hi[i] = h; g_Bn_lo[i] = l;
    }
}

// ==========================================================================
// Node kernel (unchanged best): 128 nodes/block, 256 threads, pipelined,
// B copied from global image, x4-paired B ldsm.
// ==========================================================================
#define NODE_SMEM 97536
#define NT_N 13

__global__ __launch_bounds__(256, 2)
void node_kernel(const float* __restrict__ h, const float* __restrict__ b, int N)
{
    extern __shared__ __align__(16) char sb[];
    const uint ub = smem_u32(sb);
    const int tid = threadIdx.x;
    const int wid = tid >> 5;
    const int lane = tid & 31;
    const int base = blockIdx.x * 128;

    const uint A_HI0 = 0, A_LO0 = 10240, A_HI1 = 20480, A_LO1 = 30720;
    const uint B_HI = 40960, B_LO = 69248;

    for (int i = tid; i < 1768; i += 256) {
        ((float4*)(sb + B_HI))[i] = ((const float4*)g_Bn_hi)[i];
        ((float4*)(sb + B_LO))[i] = ((const float4*)g_Bn_lo)[i];
    }

    float acc[NT_N][4];
#pragma unroll
    for (int nt = 0; nt < NT_N; nt++)
#pragma unroll
        for (int r = 0; r < 4; r++) acc[nt][r] = 0.0f;

    int pm[4], pk[4], gn[4];
#pragma unroll
    for (int it = 0; it < 4; it++) {
        int i = it * 256 + tid;
        pm[it] = i >> 3; pk[it] = (i & 7) * 4;
        int g = base + pm[it]; if (g >= N) g = N - 1;
        gn[it] = g;
    }

    float4 pf[4];
#pragma unroll
    for (int it = 0; it < 4; it++)
        pf[it] = *(const float4*)(h + (size_t)gn[it] * DIM + pk[it]);
#pragma unroll
    for (int it = 0; it < 4; it++) {
        uint2 hi, lo; split4(pf[it], hi, lo);
        *(uint2*)(sb + A_HI0 + pm[it] * 80 + pk[it] * 2) = hi;
        *(uint2*)(sb + A_LO0 + pm[it] * 80 + pk[it] * 2) = lo;
    }
#pragma unroll
    for (int it = 0; it < 4; it++)
        pf[it] = *(const float4*)(h + (size_t)gn[it] * DIM + 32 + pk[it]);
    __syncthreads();

#pragma unroll
    for (int ch = 0; ch < 4; ch++) {
        if (ch < 3) {
            const uint nh = (ch & 1) ? A_HI0 : A_HI1;
            const uint nl = (ch & 1) ? A_LO0 : A_LO1;
#pragma unroll
            for (int it = 0; it < 4; it++) {
                uint2 hi, lo; split4(pf[it], hi, lo);
                *(uint2*)(sb + nh + pm[it] * 80 + pk[it] * 2) = hi;
                *(uint2*)(sb + nl + pm[it] * 80 + pk[it] * 2) = lo;
            }
            if (ch < 2) {
#pragma unroll
                for (int it = 0; it < 4; it++)
                    pf[it] = *(const float4*)(h + (size_t)gn[it] * DIM
                                              + (ch + 2) * 32 + pk[it]);
            }
        }
        const uint AH = (ch & 1) ? A_HI1 : A_HI0;
        const uint AL = (ch & 1) ? A_LO1 : A_LO0;
#pragma unroll
        for (int kt = 0; kt < 2; kt++) {
            int ktg = ch * 2 + kt;
            uint ahi[4], alo[4];
            uint row = wid * 16 + (lane & 15);
            uint off = row * 80 + (lane >> 4) * 16 + kt * 32;
            ldsm_x4(ahi, ub + AH + off);
            ldsm_x4(alo, ub + AL + off);
            uint brow = ((lane >> 4) << 3) + (lane & 7);
            uint bk   = ((lane >> 3) & 1) * 16 + ktg * 32;
#pragma unroll
            for (int ntp = 0; ntp < 6; ntp++) {
                uint boff = (ntp * 16 + brow) * 272 + bk;
                uint bh4[4], bl4[4];
                ldsm_x4(bh4, ub + B_HI + boff);
                ldsm_x4(bl4, ub + B_LO + boff);
                mma16816(acc[2 * ntp],     ahi, bh4);
                mma16816(acc[2 * ntp],     alo, bh4);
                mma16816(acc[2 * ntp],     ahi, bl4);
                mma16816(acc[2 * ntp + 1], ahi, bh4 + 2);
                mma16816(acc[2 * ntp + 1], alo, bh4 + 2);
                mma16816(acc[2 * ntp + 1], ahi, bl4 + 2);
            }
            {
                uint l = lane & 15;
                uint boff = (96 + (l & 7)) * 272 + ((l >> 3) & 1) * 16 + ktg * 32;
                uint bhi[2], blo[2];
                ldsm_x2(bhi, ub + B_HI + boff);
                ldsm_x2(blo, ub + B_LO + boff);
                mma16816(acc[12], ahi, bhi);
                mma16816(acc[12], alo, bhi);
                mma16816(acc[12], ahi, blo);
            }
        }
        __syncthreads();
    }

    float* sOutF = (float*)sb;
    {
        int r0 = wid * 16 + (lane >> 2);
        int c0 = 2 * (lane & 3);
#pragma unroll
        for (int nt = 0; nt < NT_N; nt++) {
            *(float2*)(sOutF + r0 * 104 + nt * 8 + c0) =
                make_float2(acc[nt][0], acc[nt][1]);
            *(float2*)(sOutF + (r0 + 8) * 104 + nt * 8 + c0) =
                make_float2(acc[nt][2], acc[nt][3]);
        }
    }
    __syncthreads();

    const ull* sOutU = (const ull*)sb;   // pitch 52 ull
    const ull* b2 = (const ull*)b;
    int rv = N - base; if (rv > 128) rv = 128;
    if (rv > 0) {
        for (int i = tid; i < rv * PAIRS; i += 256) {
            int m = i / PAIRS, c = i - m * PAIRS;
            *(ull*)(g_P + (size_t)(base + m) * PPITCH + 2 * c) =
                add2(sOutU[m * 52 + c], b2[c]);
            *(ull*)(g_Q + (size_t)(base + m) * PPITCH + 2 * c) =
                sOutU[m * 52 + 25 + c];
        }
    }
}

// ==========================================================================
// Edge kernel: 256 edges/block, 256 threads (8 warps x 2 m-tiles),
// WARP-PRIVATE pipelined staging: warp w stages its own 32 rows per chunk;
// mainloop uses only __syncwarp() — zero block barriers until the epilogue.
// smem: A_HI0 @0 (12288), A_LO0 @12288, A_HI1 @24576, A_LO1 @36864,
//       B_HI @49152 (15232), B_LO @64384 (15232),
//       sS @79616 (1024), sD @80640 (1024) -> 81664.  2 blocks/SM.
// sOut overlays @0: 256x56 f32 = 57344 (A + part of B_HI, dead after loop).
// ==========================================================================
#define EDGE_SMEM 81664
#define NT_E 7

__global__ __launch_bounds__(256, 2)
void edge_kernel(const float* __restrict__ efeat,
                 const void* __restrict__ src,
                 const void* __restrict__ dst,
                 float* __restrict__ out, int E)
{
    extern __shared__ __align__(16) char sb[];
    const uint ub = smem_u32(sb);
    const int tid = threadIdx.x;
    const int wid = tid >> 5;
    const int lane = tid & 31;
    const int base = blockIdx.x * 256;

    const uint A_HI0 = 0, A_LO0 = 12288, A_HI1 = 24576, A_LO1 = 36864;
    const uint B_HI = 49152, B_LO = 64384;
    int* sS = (int*)(sb + 79616);
    int* sD = (int*)(sb + 80640);

    for (int i = tid; i < 952; i += 256) {
        ((float4*)(sb + B_HI))[i] = ((const float4*)g_Be_hi)[i];
        ((float4*)(sb + B_LO))[i] = ((const float4*)g_Be_lo)[i];
    }
    const int use64 = g_idx64;
    {
        long long g = base + tid; if (g >= E) g = E - 1;
        int s, d;
        if (use64) {
            s = (int)((const long long*)src)[g];
            d = (int)((const long long*)dst)[g];
        } else {
            s = ((const int*)src)[g];
            d = ((const int*)dst)[g];
        }
        sS[tid] = s; sD[tid] = d;
        const char* pp = (const char*)(g_P + (size_t)s * PPITCH);
        const char* qq = (const char*)(g_Q + (size_t)d * PPITCH);
        asm volatile("prefetch.global.L2 [%0];" :: "l"(pp));
        asm volatile("prefetch.global.L2 [%0];" :: "l"(pp + 128));
        asm volatile("prefetch.global.L2 [%0];" :: "l"(qq));
        asm volatile("prefetch.global.L2 [%0];" :: "l"(qq + 128));
    }
    __syncthreads();   // B images + idx visible to everyone (once)

    float acc[2][NT_E][4];
#pragma unroll
    for (int mt = 0; mt < 2; mt++)
#pragma unroll
        for (int nt = 0; nt < NT_E; nt++)
#pragma unroll
            for (int r = 0; r < 4; r++) acc[mt][nt][r] = 0.0f;

    // warp-private staging: warp w owns rows [32w, 32w+32); per chunk
    // 32 rows x 16 k = 128 float4 -> 4 per lane.
    int pm[4], pk[4]; long long ge[4];
#pragma unroll
    for (int it = 0; it < 4; it++) {
        int idx = it * 32 + lane;           // 0..127
        pm[it] = wid * 32 + (idx >> 2);     // row in block tile
        pk[it] = (idx & 3) * 4;             // k offset (floats) within chunk
        long long g = base + pm[it]; if (g >= E) g = E - 1;
        ge[it] = g;
    }

    float4 pf[4];
    // prologue: chunk 0 -> buf0, prefetch chunk 1
#pragma unroll
    for (int it = 0; it < 4; it++)
        pf[it] = *(const float4*)(efeat + (size_t)ge[it] * DIM + pk[it]);
#pragma unroll
    for (int it = 0; it < 4; it++) {
        uint2 hi, lo; split4(pf[it], hi, lo);
        *(uint2*)(sb + A_HI0 + pm[it] * 48 + pk[it] * 2) = hi;
        *(uint2*)(sb + A_LO0 + pm[it] * 48 + pk[it] * 2) = lo;
    }
#pragma unroll
    for (int it = 0; it < 4; it++)
        pf[it] = *(const float4*)(efeat + (size_t)ge[it] * DIM + 16 + pk[it]);
    __syncwarp();

#pragma unroll
    for (int ch = 0; ch < 8; ch++) {
        if (ch < 7) {
            const uint nh = (ch & 1) ? A_HI0 : A_HI1;
            const uint nl = (ch & 1) ? A_LO0 : A_LO1;
#pragma unroll
            for (int it = 0; it < 4; it++) {
                uint2 hi, lo; split4(pf[it], hi, lo);
                *(uint2*)(sb + nh + pm[it] * 48 + pk[it] * 2) = hi;
                *(uint2*)(sb + nl + pm[it] * 48 + pk[it] * 2) = lo;
            }
            if (ch < 6) {
#pragma unroll
                for (int it = 0; it < 4; it++)
                    pf[it] = *(const float4*)(efeat + (size_t)ge[it] * DIM
                                              + (ch + 2) * 16 + pk[it]);
            }
        }
        __syncwarp();   // our own stores (prev chunk's buffer) visible warp-wide
        const uint AH = (ch & 1) ? A_HI1 : A_HI0;
        const uint AL = (ch & 1) ? A_LO1 : A_LO0;

        uint ahi[2][4], alo[2][4];
#pragma unroll
        for (int mt = 0; mt < 2; mt++) {
            uint row = wid * 32 + mt * 16 + (lane & 15);
            uint off = row * 48 + (lane >> 4) * 16;
            ldsm_x4(ahi[mt], ub + AH + off);
            ldsm_x4(alo[mt], ub + AL + off);
        }
#pragma unroll
        for (int nt = 0; nt < NT_E; nt++) {
            uint l = lane & 15;
            uint boff = (nt * 8 + (l & 7)) * 272 + ((l >> 3) & 1) * 16 + ch * 32;
            uint bhi[2], blo[2];
            ldsm_x2(bhi, ub + B_HI + boff);
            ldsm_x2(blo, ub + B_LO + boff);
#pragma unroll
            for (int mt = 0; mt < 2; mt++) {
                mma16816(acc[mt][nt], ahi[mt], bhi);
                mma16816(acc[mt][nt], alo[mt], bhi);
                mma16816(acc[mt][nt], ahi[mt], blo);
            }
        }
    }

    // one block barrier: everyone done with A bufs + B images
    __syncthreads();

    // frags -> sOut [256][56] f32
    float* sOutF = (float*)sb;
#pragma unroll
    for (int mt = 0; mt < 2; mt++) {
        int r0 = wid * 32 + mt * 16 + (lane >> 2);
        int c0 = 2 * (lane & 3);
#pragma unroll
        for (int nt = 0; nt < NT_E; nt++) {
            *(float2*)(sOutF + r0 * 56 + nt * 8 + c0) =
                make_float2(acc[mt][nt][0], acc[mt][nt][1]);
            *(float2*)(sOutF + (r0 + 8) * 56 + nt * 8 + c0) =
                make_float2(acc[mt][nt][2], acc[mt][nt][3]);
        }
    }
    __syncthreads();

    const ull* sOutU = (const ull*)sb;   // pitch 28 ull
    int rv = E - base; if (rv > 256) rv = 256;
    if (rv > 0) {
        for (int i = tid; i < rv * PAIRS; i += 256) {
            int row = i / PAIRS, c = i - row * PAIRS;
            ull pv = *(const ull*)(g_P + (size_t)sS[row] * PPITCH + 2 * c);
            ull qv = *(const ull*)(g_Q + (size_t)sD[row] * PPITCH + 2 * c);
            *(ull*)(out + (size_t)(base + row) * NCLS + 2 * c) =
                add2(add2(pv, qv), sOutU[row * 28 + c]);
        }
    }
}

// --------------------------------------------------------------------------
extern "C" void kernel_launch(void* const* d_in, const int* in_sizes, int n_in,
                              void* d_out, int out_size)
{
    const float* h   = (const float*)d_in[0];
    const float* e   = (const float*)d_in[1];
    const void*  src = d_in[2];
    const void*  dst = d_in[3];
    const float* W   = (const float*)d_in[4];
    const float* b   = (const float*)d_in[5];

    int N = in_sizes[0] / DIM;   // 50000
    int E = in_sizes[1] / DIM;   // 500000
    if (N > NMAX) N = NMAX;

    static int attr_done = 0;
    if (!attr_done) {
        cudaFuncSetAttribute(node_kernel, cudaFuncAttributeMaxDynamicSharedMemorySize, NODE_SMEM);
        cudaFuncSetAttribute(edge_kernel, cudaFuncAttributeMaxDynamicSharedMemorySize, EDGE_SMEM);
        attr_done = 1;
    }

    setup_kernel<<<64, 256>>>(W, src, E);
    node_kernel<<<(N + 127) / 128, 256, NODE_SMEM>>>(h, b, N);
    edge_kernel<<<(E + 255) / 256, 256, EDGE_SMEM>>>(e, src, dst, (float*)d_out, E);
}